// round 3
// baseline (speedup 1.0000x reference)
#include <cuda_runtime.h>
#include <math.h>

#define L 512
#define NCON 20
#define INV_TEMP (1.0f / 0.07f)
#define MAXROWS 32768
#define MAXB_A 256
#define MAXB_B 2048

// scratch (device globals; no allocation allowed)
__device__ float g_ebar[2][L];            // mean concept embedding per branch
__device__ int   g_cnt0[MAXROWS];         // histogram of sz_idx   (zeroed by last block each run)
__device__ int   g_cnt1[MAXROWS];         // histogram of nsz_idx
__device__ float g_pA[MAXB_A];            // kernel A per-block partials (log-den terms, pre-scaled)
__device__ float g_pB[MAXB_B];            // rowpass per-block partials
__device__ unsigned int g_count = 0;      // last-block counter (reset by last block)

// ---------------------------------------------------------------------------
// Kernel A: independent of rowpass.
//  - blocks [0, nA): gathered log(den) partial sums + index histograms.
//    den_i = sum_{c not in P} exp(corr[r_i][c]/tau); val = log(den)/Nbranch.
//  - block nA: computes e_bar vectors (mean of selected concept embeddings,
//    duplicates counted).
// ---------------------------------------------------------------------------
__global__ void kernelA(const int* __restrict__ sz_idx, int Ns,
                        const int* __restrict__ nsz_idx, int Nn,
                        const float* __restrict__ corr,
                        const float* __restrict__ all_emb,
                        const int* __restrict__ Psz, int nPsz,
                        const int* __restrict__ Pnsz, int nPnsz,
                        int Bsz, int nA, float invNs, float invNn) {
    int b = blockIdx.x;

    if (b == nA) {  // e_bar block
        for (int t = threadIdx.x; t < L; t += blockDim.x) {
            float s0 = 0.0f, s1 = 0.0f;
            for (int j = 0; j < nPsz; j++)  s0 += all_emb[Psz[j] * L + t];
            for (int j = 0; j < nPnsz; j++) s1 += all_emb[Pnsz[j] * L + t];
            g_ebar[0][t] = s0 / (float)nPsz;
            g_ebar[1][t] = s1 / (float)nPnsz;
        }
        return;
    }

    int branch = (b >= Bsz) ? 1 : 0;
    int base = (branch ? (b - Bsz) : b) * (int)blockDim.x;
    int i = base + threadIdx.x;
    const int* idxp = branch ? nsz_idx : sz_idx;
    int count = branch ? Nn : Ns;
    const int* P = branch ? Pnsz : Psz;
    int nP = branch ? nPnsz : nPsz;

    // bitmask of excluded concepts (NCON = 20 <= 32)
    unsigned int mask = 0u;
    for (int j = 0; j < nP; j++) mask |= 1u << P[j];

    float val = 0.0f;
    if (i < count) {
        int r = idxp[i];
        atomicAdd(branch ? &g_cnt1[r] : &g_cnt0[r], 1);
        const float* cr = corr + (size_t)r * NCON;
        float den = 0.0f;
#pragma unroll
        for (int c = 0; c < NCON; c++)
            if (!((mask >> c) & 1u)) den += __expf(cr[c] * INV_TEMP);
        val = logf(den) * (branch ? invNn : invNs);
    }

    // fixed-tree block reduction (deterministic)
    __shared__ float sh[256];
    sh[threadIdx.x] = val;
    __syncthreads();
    for (int s = 128; s > 0; s >>= 1) {
        if (threadIdx.x < s) sh[threadIdx.x] += sh[threadIdx.x + s];
        __syncthreads();
    }
    if (threadIdx.x == 0) g_pA[b] = sh[0];
}

// ---------------------------------------------------------------------------
// Kernel B: streaming pass over hg (the 64 MB HBM-bound kernel) + finalize.
// One warp per row. Computes ss, d0, d1 in registers; contributes
//   -invn/tau * (cnt0[r]*d0/Ns + cnt1[r]*d1/Nn)
// directly (sum over sampled indices == cnt-weighted sum over rows).
// Last block reduces all partials (fixed order -> deterministic), writes out,
// then zeroes histograms + counter for the next graph replay.
// ---------------------------------------------------------------------------
__global__ void rowpass_fin_kernel(const float* __restrict__ hg, int nrows,
                                   int nA, int nB, float cs, float cn,
                                   float* __restrict__ out) {
    int warp = (blockIdx.x * blockDim.x + threadIdx.x) >> 5;  // global row
    int lane = threadIdx.x & 31;
    int wib = threadIdx.x >> 5;  // warp-in-block (0..15)

    float val = 0.0f;
    if (warp < nrows) {
        const float4* row = reinterpret_cast<const float4*>(hg + (size_t)warp * L);
        const float4* e0p = reinterpret_cast<const float4*>(g_ebar[0]);
        const float4* e1p = reinterpret_cast<const float4*>(g_ebar[1]);

        float ss = 0.0f, d0 = 0.0f, d1 = 0.0f;
#pragma unroll
        for (int it = 0; it < 4; it++) {
            int idx = it * 32 + lane;
            float4 v  = row[idx];
            float4 e0 = e0p[idx];
            float4 e1 = e1p[idx];
            ss = fmaf(v.x, v.x, fmaf(v.y, v.y, fmaf(v.z, v.z, fmaf(v.w, v.w, ss))));
            d0 = fmaf(v.x, e0.x, fmaf(v.y, e0.y, fmaf(v.z, e0.z, fmaf(v.w, e0.w, d0))));
            d1 = fmaf(v.x, e1.x, fmaf(v.y, e1.y, fmaf(v.z, e1.z, fmaf(v.w, e1.w, d1))));
        }
#pragma unroll
        for (int o = 16; o > 0; o >>= 1) {
            ss += __shfl_xor_sync(0xffffffffu, ss, o);
            d0 += __shfl_xor_sync(0xffffffffu, d0, o);
            d1 += __shfl_xor_sync(0xffffffffu, d1, o);
        }
        if (lane == 0) {
            int c0 = g_cnt0[warp];
            int c1 = g_cnt1[warp];
            if (c0 | c1) {
                float invn = 1.0f / fmaxf(sqrtf(ss), 1e-12f);
                val = -invn * ((float)c0 * d0 * cs + (float)c1 * d1 * cn);
            }
        }
    }

    __shared__ float sw[16];
    __shared__ float sh[512];
    __shared__ bool is_last;
    if (lane == 0) sw[wib] = val;
    __syncthreads();
    if (threadIdx.x == 0) {
        float s = 0.0f;
#pragma unroll
        for (int k = 0; k < 16; k++) s += sw[k];
        g_pB[blockIdx.x] = s;
        __threadfence();
        unsigned int done = atomicAdd(&g_count, 1u);
        is_last = (done == gridDim.x - 1);
    }
    __syncthreads();

    if (is_last) {
        __threadfence();  // see all blocks' partials
        int t = threadIdx.x;  // 512 threads
        float acc = (t < nA) ? g_pA[t] : 0.0f;
        for (int j = t; j < nB; j += 512) acc += g_pB[j];  // fixed order
        sh[t] = acc;
        __syncthreads();
        for (int s = 256; s > 0; s >>= 1) {
            if (t < s) sh[t] += sh[t + s];
            __syncthreads();
        }
        if (t == 0) out[0] = sh[0];
        // reset scratch for next graph replay (deterministic: one block only)
        for (int j = t; j < nrows; j += 512) { g_cnt0[j] = 0; g_cnt1[j] = 0; }
        if (t == 0) g_count = 0u;
    }
}

extern "C" void kernel_launch(void* const* d_in, const int* in_sizes, int n_in,
                              void* d_out, int out_size) {
    const float* hg       = (const float*)d_in[0];
    const float* corr     = (const float*)d_in[1];
    const float* all_emb  = (const float*)d_in[2];
    const int*   sz_idx   = (const int*)d_in[3];
    const int*   nsz_idx  = (const int*)d_in[4];
    const int*   Psz_idx  = (const int*)d_in[5];
    const int*   Pnsz_idx = (const int*)d_in[6];
    float* out = (float*)d_out;

    int nrows = in_sizes[0] / L;          // 32768
    int Ns    = in_sizes[3];
    int Nn    = in_sizes[4];
    int nPsz  = in_sizes[5];
    int nPnsz = in_sizes[6];

    float invNs = 1.0f / (float)Ns;
    float invNn = 1.0f / (float)Nn;

    int Bsz = (Ns + 255) / 256;
    int Bn  = (Nn + 255) / 256;
    int nA  = Bsz + Bn;                   // gather blocks; block nA = ebar
    kernelA<<<nA + 1, 256>>>(sz_idx, Ns, nsz_idx, Nn, corr, all_emb,
                             Psz_idx, nPsz, Pnsz_idx, nPnsz,
                             Bsz, nA, invNs, invNn);

    int nB = (nrows + 15) / 16;           // 512 threads = 16 rows per block
    rowpass_fin_kernel<<<nB, 512>>>(hg, nrows, nA, nB,
                                    INV_TEMP * invNs, INV_TEMP * invNn, out);
}

// round 4
// speedup vs baseline: 1.3439x; 1.3439x over previous
#include <cuda_runtime.h>
#include <math.h>

#define L 512
#define NCON 20
#define INV_TEMP (1.0f / 0.07f)
#define MAXROWS 32768
#define MAXB_G 256

// scratch (device globals; no allocation allowed)
__device__ float g_ebar[2][L];          // mean concept embedding per branch
__device__ unsigned int g_mask[2];      // bitmask of excluded concepts per branch
__device__ float g_v0[MAXROWS];         // <row, ebar_sz>  / max(||row||,1e-12)
__device__ float g_v1[MAXROWS];         // <row, ebar_nsz> / max(||row||,1e-12)
__device__ float g_pG[MAXB_G];          // gather per-block partials (pre-scaled)
__device__ unsigned int g_count = 0;    // last-block counter (reset by kernel 1)

// ---------------------------------------------------------------------------
// Kernel 1: ebar vectors (1 block, 512 threads: one component per thread,
// 10 independent loads -> latency-parallel), exclusion bitmasks, counter reset.
// ---------------------------------------------------------------------------
__global__ void ebar_kernel(const float* __restrict__ all_emb,
                            const int* __restrict__ Psz, int nPsz,
                            const int* __restrict__ Pnsz, int nPnsz) {
    int t = threadIdx.x;  // 0..511 == 0..L-1
    float s0 = 0.0f, s1 = 0.0f;
#pragma unroll 5
    for (int j = 0; j < nPsz; j++)  s0 += all_emb[Psz[j] * L + t];
#pragma unroll 5
    for (int j = 0; j < nPnsz; j++) s1 += all_emb[Pnsz[j] * L + t];
    g_ebar[0][t] = s0 / (float)nPsz;
    g_ebar[1][t] = s1 / (float)nPnsz;
    if (t == 0) {
        unsigned int m0 = 0u, m1 = 0u;
        for (int j = 0; j < nPsz; j++)  m0 |= 1u << Psz[j];
        for (int j = 0; j < nPnsz; j++) m1 |= 1u << Pnsz[j];
        g_mask[0] = m0;
        g_mask[1] = m1;
        g_count = 0u;  // reset for this replay's gather_finalize
    }
}

// ---------------------------------------------------------------------------
// Kernel 2: streaming pass over hg (L2-resident in the replay loop).
// One warp per row, 256 threads/block. Stores the two normalized dots.
// ---------------------------------------------------------------------------
__global__ void rowpass_kernel(const float* __restrict__ hg, int nrows) {
    int warp = (blockIdx.x * blockDim.x + threadIdx.x) >> 5;
    int lane = threadIdx.x & 31;
    if (warp >= nrows) return;

    const float4* row = reinterpret_cast<const float4*>(hg + (size_t)warp * L);
    const float4* e0p = reinterpret_cast<const float4*>(g_ebar[0]);
    const float4* e1p = reinterpret_cast<const float4*>(g_ebar[1]);

    float ss = 0.0f, d0 = 0.0f, d1 = 0.0f;
#pragma unroll
    for (int it = 0; it < 4; it++) {
        int idx = it * 32 + lane;
        float4 v  = row[idx];
        float4 e0 = e0p[idx];
        float4 e1 = e1p[idx];
        ss = fmaf(v.x, v.x, fmaf(v.y, v.y, fmaf(v.z, v.z, fmaf(v.w, v.w, ss))));
        d0 = fmaf(v.x, e0.x, fmaf(v.y, e0.y, fmaf(v.z, e0.z, fmaf(v.w, e0.w, d0))));
        d1 = fmaf(v.x, e1.x, fmaf(v.y, e1.y, fmaf(v.z, e1.z, fmaf(v.w, e1.w, d1))));
    }
#pragma unroll
    for (int o = 16; o > 0; o >>= 1) {
        ss += __shfl_xor_sync(0xffffffffu, ss, o);
        d0 += __shfl_xor_sync(0xffffffffu, d0, o);
        d1 += __shfl_xor_sync(0xffffffffu, d1, o);
    }
    if (lane == 0) {
        float invn = 1.0f / fmaxf(sqrtf(ss), 1e-12f);
        g_v0[warp] = d0 * invn;
        g_v1[warp] = d1 * invn;
    }
}

// ---------------------------------------------------------------------------
// Kernel 3: gathered per-index terms + last-block finalize.
// term_i = log(den_i) - v[r]/tau, scaled by 1/Nbranch. Deterministic:
// fixed-tree block reductions, fixed-order final reduce; counter is reset by
// kernel 1 of the NEXT replay, so no tail work here beyond the reduce.
// ---------------------------------------------------------------------------
__global__ void gather_finalize_kernel(const int* __restrict__ sz_idx, int Ns,
                                       const int* __restrict__ nsz_idx, int Nn,
                                       const float* __restrict__ corr, int Bsz,
                                       float invNs, float invNn,
                                       float* __restrict__ out) {
    int b = blockIdx.x;
    int branch = (b < Bsz) ? 0 : 1;
    int base = (branch ? (b - Bsz) : b) * (int)blockDim.x;
    int i = base + threadIdx.x;
    const int* idxp = branch ? nsz_idx : sz_idx;
    int count = branch ? Nn : Ns;
    unsigned int mask = g_mask[branch];
    float scale = branch ? invNn : invNs;

    float val = 0.0f;
    if (i < count) {
        int r = idxp[i];
        float v = branch ? g_v1[r] : g_v0[r];
        const float* cr = corr + (size_t)r * NCON;
        float den = 0.0f;
#pragma unroll
        for (int c = 0; c < NCON; c++)
            if (!((mask >> c) & 1u)) den += __expf(cr[c] * INV_TEMP);
        val = (logf(den) - v * INV_TEMP) * scale;
    }

    // fixed-tree block reduction (deterministic)
    __shared__ float sh[256];
    __shared__ bool is_last;
    sh[threadIdx.x] = val;
    __syncthreads();
    for (int s = 128; s > 0; s >>= 1) {
        if (threadIdx.x < s) sh[threadIdx.x] += sh[threadIdx.x + s];
        __syncthreads();
    }
    if (threadIdx.x == 0) {
        g_pG[b] = sh[0];
        __threadfence();
        unsigned int done = atomicAdd(&g_count, 1u);
        is_last = (done == gridDim.x - 1);
    }
    __syncthreads();

    if (is_last) {
        __threadfence();  // see all blocks' partials
        int t = threadIdx.x;
        int Btot = gridDim.x;
        sh[t] = (t < Btot) ? g_pG[t] : 0.0f;
        __syncthreads();
        for (int s = 128; s > 0; s >>= 1) {
            if (t < s) sh[t] += sh[t + s];
            __syncthreads();
        }
        if (t == 0) out[0] = sh[0];
    }
}

extern "C" void kernel_launch(void* const* d_in, const int* in_sizes, int n_in,
                              void* d_out, int out_size) {
    const float* hg       = (const float*)d_in[0];
    const float* corr     = (const float*)d_in[1];
    const float* all_emb  = (const float*)d_in[2];
    const int*   sz_idx   = (const int*)d_in[3];
    const int*   nsz_idx  = (const int*)d_in[4];
    const int*   Psz_idx  = (const int*)d_in[5];
    const int*   Pnsz_idx = (const int*)d_in[6];
    float* out = (float*)d_out;

    int nrows = in_sizes[0] / L;          // 32768
    int Ns    = in_sizes[3];
    int Nn    = in_sizes[4];
    int nPsz  = in_sizes[5];
    int nPnsz = in_sizes[6];

    ebar_kernel<<<1, L>>>(all_emb, Psz_idx, nPsz, Pnsz_idx, nPnsz);

    int blocks = (nrows + 7) / 8;         // 256 threads = 8 rows/block (R1 config)
    rowpass_kernel<<<blocks, 256>>>(hg, nrows);

    int Bsz = (Ns + 255) / 256;
    int Bn  = (Nn + 255) / 256;
    gather_finalize_kernel<<<Bsz + Bn, 256>>>(sz_idx, Ns, nsz_idx, Nn, corr, Bsz,
                                              1.0f / (float)Ns, 1.0f / (float)Nn,
                                              out);
}

// round 5
// speedup vs baseline: 1.4875x; 1.1068x over previous
#include <cuda_runtime.h>
#include <math.h>

#define L 512
#define NCON 20
#define INV_TEMP (1.0f / 0.07f)
#define MAXROWS 32768
#define MAXB_G 256
#define RP_BLOCKS 592   // 4 blocks/SM on 148 SMs
#define RP_THREADS 256

// scratch (device globals; no allocation allowed)
__device__ float g_v0[MAXROWS];         // <row, ebar_sz>  / max(||row||,1e-12)
__device__ float g_v1[MAXROWS];         // <row, ebar_nsz> / max(||row||,1e-12)
__device__ float g_pG[MAXB_G];          // gather per-block partials (pre-scaled)
__device__ unsigned int g_count = 0;    // last-block counter (reset by rowpass)

// ---------------------------------------------------------------------------
// Kernel 1: grid-stride rowpass. Each block first builds ebar_sz/ebar_nsz in
// shared memory (10 concept rows = 20 KB of L2-hot all_emb, overlapped across
// 592 blocks -> no serial latency chain), then streams its rows of hg
// (L2-resident across replays), writing the two normalized dots per row.
// Also resets the last-block counter for this replay's gather (safe: rowpass
// completes before gather launches in-stream).
// ---------------------------------------------------------------------------
__global__ void __launch_bounds__(RP_THREADS)
rowpass_kernel(const float* __restrict__ hg, int nrows,
               const float* __restrict__ all_emb,
               const int* __restrict__ Psz, int nPsz,
               const int* __restrict__ Pnsz, int nPnsz) {
    __shared__ float se0[L];
    __shared__ float se1[L];
    __shared__ int sp[2][16];
    int tid = threadIdx.x;

    if (blockIdx.x == 0 && tid == 0) g_count = 0u;

    if (tid < nPsz)                    sp[0][tid]      = Psz[tid];
    if (tid >= 32 && tid - 32 < nPnsz) sp[1][tid - 32] = Pnsz[tid - 32];
    __syncthreads();

    // build ebar into smem: 256 threads x 2 components each
    for (int t = tid; t < L; t += RP_THREADS) {
        float s0 = 0.0f, s1 = 0.0f;
        for (int j = 0; j < nPsz; j++)  s0 += all_emb[sp[0][j] * L + t];
        for (int j = 0; j < nPnsz; j++) s1 += all_emb[sp[1][j] * L + t];
        se0[t] = s0 / (float)nPsz;
        se1[t] = s1 / (float)nPnsz;
    }
    __syncthreads();

    int wg   = (blockIdx.x * RP_THREADS + tid) >> 5;   // global warp id
    int lane = tid & 31;
    int nwarps = (gridDim.x * RP_THREADS) >> 5;
    const float4* e0p = reinterpret_cast<const float4*>(se0);
    const float4* e1p = reinterpret_cast<const float4*>(se1);

    for (int row = wg; row < nrows; row += nwarps) {
        const float4* rp = reinterpret_cast<const float4*>(hg + (size_t)row * L);
        float ss = 0.0f, d0 = 0.0f, d1 = 0.0f;
#pragma unroll
        for (int it = 0; it < 4; it++) {
            int idx = it * 32 + lane;
            float4 v  = rp[idx];
            float4 e0 = e0p[idx];
            float4 e1 = e1p[idx];
            ss = fmaf(v.x, v.x, fmaf(v.y, v.y, fmaf(v.z, v.z, fmaf(v.w, v.w, ss))));
            d0 = fmaf(v.x, e0.x, fmaf(v.y, e0.y, fmaf(v.z, e0.z, fmaf(v.w, e0.w, d0))));
            d1 = fmaf(v.x, e1.x, fmaf(v.y, e1.y, fmaf(v.z, e1.z, fmaf(v.w, e1.w, d1))));
        }
#pragma unroll
        for (int o = 16; o > 0; o >>= 1) {
            ss += __shfl_xor_sync(0xffffffffu, ss, o);
            d0 += __shfl_xor_sync(0xffffffffu, d0, o);
            d1 += __shfl_xor_sync(0xffffffffu, d1, o);
        }
        if (lane == 0) {
            float invn = 1.0f / fmaxf(sqrtf(ss), 1e-12f);
            g_v0[row] = d0 * invn;
            g_v1[row] = d1 * invn;
        }
    }
}

// ---------------------------------------------------------------------------
// Kernel 2: gathered per-index terms + last-block finalize.
// term_i = log(den_i) - v[r]/tau, scaled by 1/Nbranch. Exclusion mask built
// inline from P indices (broadcast loads). Deterministic: fixed-tree block
// reductions, fixed-order final reduce.
// ---------------------------------------------------------------------------
__global__ void gather_finalize_kernel(const int* __restrict__ sz_idx, int Ns,
                                       const int* __restrict__ nsz_idx, int Nn,
                                       const float* __restrict__ corr, int Bsz,
                                       const int* __restrict__ Psz, int nPsz,
                                       const int* __restrict__ Pnsz, int nPnsz,
                                       float invNs, float invNn,
                                       float* __restrict__ out) {
    int b = blockIdx.x;
    int branch = (b < Bsz) ? 0 : 1;
    int base = (branch ? (b - Bsz) : b) * (int)blockDim.x;
    int i = base + threadIdx.x;
    const int* idxp = branch ? nsz_idx : sz_idx;
    int count = branch ? Nn : Ns;
    const int* P = branch ? Pnsz : Psz;
    int nP = branch ? nPnsz : nPsz;
    float scale = branch ? invNn : invNs;

    unsigned int mask = 0u;
    for (int j = 0; j < nP; j++) mask |= 1u << P[j];

    float val = 0.0f;
    if (i < count) {
        int r = idxp[i];
        float v = branch ? g_v1[r] : g_v0[r];
        const float* cr = corr + (size_t)r * NCON;
        float den = 0.0f;
#pragma unroll
        for (int c = 0; c < NCON; c++)
            if (!((mask >> c) & 1u)) den += __expf(cr[c] * INV_TEMP);
        val = (logf(den) - v * INV_TEMP) * scale;
    }

    // fixed-tree block reduction (deterministic)
    __shared__ float sh[256];
    __shared__ bool is_last;
    sh[threadIdx.x] = val;
    __syncthreads();
    for (int s = 128; s > 0; s >>= 1) {
        if (threadIdx.x < s) sh[threadIdx.x] += sh[threadIdx.x + s];
        __syncthreads();
    }
    if (threadIdx.x == 0) {
        g_pG[b] = sh[0];
        __threadfence();
        unsigned int done = atomicAdd(&g_count, 1u);
        is_last = (done == gridDim.x - 1);
    }
    __syncthreads();

    if (is_last) {
        __threadfence();  // see all blocks' partials
        int t = threadIdx.x;
        int Btot = gridDim.x;
        sh[t] = (t < Btot) ? g_pG[t] : 0.0f;
        __syncthreads();
        for (int s = 128; s > 0; s >>= 1) {
            if (t < s) sh[t] += sh[t + s];
            __syncthreads();
        }
        if (t == 0) out[0] = sh[0];
    }
}

extern "C" void kernel_launch(void* const* d_in, const int* in_sizes, int n_in,
                              void* d_out, int out_size) {
    const float* hg       = (const float*)d_in[0];
    const float* corr     = (const float*)d_in[1];
    const float* all_emb  = (const float*)d_in[2];
    const int*   sz_idx   = (const int*)d_in[3];
    const int*   nsz_idx  = (const int*)d_in[4];
    const int*   Psz_idx  = (const int*)d_in[5];
    const int*   Pnsz_idx = (const int*)d_in[6];
    float* out = (float*)d_out;

    int nrows = in_sizes[0] / L;          // 32768
    int Ns    = in_sizes[3];
    int Nn    = in_sizes[4];
    int nPsz  = in_sizes[5];
    int nPnsz = in_sizes[6];

    rowpass_kernel<<<RP_BLOCKS, RP_THREADS>>>(hg, nrows, all_emb,
                                              Psz_idx, nPsz, Pnsz_idx, nPnsz);

    int Bsz = (Ns + 255) / 256;
    int Bn  = (Nn + 255) / 256;
    gather_finalize_kernel<<<Bsz + Bn, 256>>>(sz_idx, Ns, nsz_idx, Nn, corr, Bsz,
                                              Psz_idx, nPsz, Pnsz_idx, nPnsz,
                                              1.0f / (float)Ns, 1.0f / (float)Nn,
                                              out);
}

// round 6
// speedup vs baseline: 1.5025x; 1.0101x over previous
#include <cuda_runtime.h>
#include <math.h>

#define L 512
#define NCON 20
#define INV_TEMP (1.0f / 0.07f)
#define MAXROWS 32768
#define MAXB_G 256
#define RP_BLOCKS 592   // 4 blocks/SM on 148 SMs
#define RP_THREADS 256

// scratch (device globals; no allocation allowed)
__device__ float g_t0[MAXROWS];         // per-row complete sz term: log(den0) - d0*invn/tau
__device__ float g_t1[MAXROWS];         // per-row complete nsz term
__device__ float g_pG[MAXB_G];          // gather per-block partials (pre-scaled)
__device__ unsigned int g_count = 0;    // last-block counter (reset by rowpass)

// ---------------------------------------------------------------------------
// Kernel 1: grid-stride rowpass. Each block builds ebar_sz/ebar_nsz in shared
// memory (10 concept rows of L2-hot all_emb, overlapped across 592 blocks),
// then streams its rows of hg (L2-resident across replays). Per row it ALSO
// loads the 20 corr values (80 B coalesced, lanes 0..19), computes the two
// masked exp-sum denominators on the idle MUFU pipe, and writes the COMPLETE
// per-row loss terms t0/t1. Counter reset for this replay's gather included.
// ---------------------------------------------------------------------------
__global__ void __launch_bounds__(RP_THREADS)
rowpass_kernel(const float* __restrict__ hg, int nrows,
               const float* __restrict__ corr,
               const float* __restrict__ all_emb,
               const int* __restrict__ Psz, int nPsz,
               const int* __restrict__ Pnsz, int nPnsz) {
    __shared__ float se0[L];
    __shared__ float se1[L];
    __shared__ int sp[2][16];
    int tid = threadIdx.x;

    if (blockIdx.x == 0 && tid == 0) g_count = 0u;

    if (tid < nPsz)                    sp[0][tid]      = Psz[tid];
    if (tid >= 32 && tid - 32 < nPnsz) sp[1][tid - 32] = Pnsz[tid - 32];
    __syncthreads();

    // exclusion bitmasks (uniform per warp; computed from smem, cheap)
    unsigned int mask0 = 0u, mask1 = 0u;
    for (int j = 0; j < nPsz; j++)  mask0 |= 1u << sp[0][j];
    for (int j = 0; j < nPnsz; j++) mask1 |= 1u << sp[1][j];

    // build ebar into smem
    for (int t = tid; t < L; t += RP_THREADS) {
        float s0 = 0.0f, s1 = 0.0f;
        for (int j = 0; j < nPsz; j++)  s0 += all_emb[sp[0][j] * L + t];
        for (int j = 0; j < nPnsz; j++) s1 += all_emb[sp[1][j] * L + t];
        se0[t] = s0 / (float)nPsz;
        se1[t] = s1 / (float)nPnsz;
    }
    __syncthreads();

    int wg   = (blockIdx.x * RP_THREADS + tid) >> 5;   // global warp id
    int lane = tid & 31;
    int nwarps = (gridDim.x * RP_THREADS) >> 5;
    const float4* e0p = reinterpret_cast<const float4*>(se0);
    const float4* e1p = reinterpret_cast<const float4*>(se1);
    bool active = lane < NCON;
    float w0m = (active && !((mask0 >> lane) & 1u)) ? 1.0f : 0.0f;
    float w1m = (active && !((mask1 >> lane) & 1u)) ? 1.0f : 0.0f;

    for (int row = wg; row < nrows; row += nwarps) {
        // denominators: lanes 0..19 each handle one concept
        float e = active ? __expf(corr[row * NCON + lane] * INV_TEMP) : 0.0f;
        float den0 = e * w0m;
        float den1 = e * w1m;

        const float4* rp = reinterpret_cast<const float4*>(hg + (size_t)row * L);
        float ss = 0.0f, d0 = 0.0f, d1 = 0.0f;
#pragma unroll
        for (int it = 0; it < 4; it++) {
            int idx = it * 32 + lane;
            float4 v  = rp[idx];
            float4 e0 = e0p[idx];
            float4 e1 = e1p[idx];
            ss = fmaf(v.x, v.x, fmaf(v.y, v.y, fmaf(v.z, v.z, fmaf(v.w, v.w, ss))));
            d0 = fmaf(v.x, e0.x, fmaf(v.y, e0.y, fmaf(v.z, e0.z, fmaf(v.w, e0.w, d0))));
            d1 = fmaf(v.x, e1.x, fmaf(v.y, e1.y, fmaf(v.z, e1.z, fmaf(v.w, e1.w, d1))));
        }
#pragma unroll
        for (int o = 16; o > 0; o >>= 1) {
            ss   += __shfl_xor_sync(0xffffffffu, ss, o);
            d0   += __shfl_xor_sync(0xffffffffu, d0, o);
            d1   += __shfl_xor_sync(0xffffffffu, d1, o);
            den0 += __shfl_xor_sync(0xffffffffu, den0, o);
            den1 += __shfl_xor_sync(0xffffffffu, den1, o);
        }
        if (lane == 0) {
            float invn = 1.0f / fmaxf(sqrtf(ss), 1e-12f);
            g_t0[row] = __logf(den0) - d0 * invn * INV_TEMP;
            g_t1[row] = __logf(den1) - d1 * invn * INV_TEMP;
        }
    }
}

// ---------------------------------------------------------------------------
// Kernel 2: trivial gather-sum + last-block finalize.
// val_i = t_branch[r_i] / Nbranch. One idx load + one gathered float per
// thread. Deterministic fixed-tree reductions.
// ---------------------------------------------------------------------------
__global__ void gather_finalize_kernel(const int* __restrict__ sz_idx, int Ns,
                                       const int* __restrict__ nsz_idx, int Nn,
                                       int Bsz, float invNs, float invNn,
                                       float* __restrict__ out) {
    int b = blockIdx.x;
    int branch = (b < Bsz) ? 0 : 1;
    int base = (branch ? (b - Bsz) : b) * (int)blockDim.x;
    int i = base + threadIdx.x;
    const int* idxp = branch ? nsz_idx : sz_idx;
    int count = branch ? Nn : Ns;
    const float* tp = branch ? g_t1 : g_t0;
    float scale = branch ? invNn : invNs;

    float val = 0.0f;
    if (i < count) val = tp[idxp[i]] * scale;

    // fixed-tree block reduction (deterministic)
    __shared__ float sh[256];
    __shared__ bool is_last;
    sh[threadIdx.x] = val;
    __syncthreads();
    for (int s = 128; s > 0; s >>= 1) {
        if (threadIdx.x < s) sh[threadIdx.x] += sh[threadIdx.x + s];
        __syncthreads();
    }
    if (threadIdx.x == 0) {
        g_pG[b] = sh[0];
        __threadfence();
        unsigned int done = atomicAdd(&g_count, 1u);
        is_last = (done == gridDim.x - 1);
    }
    __syncthreads();

    if (is_last) {
        __threadfence();  // see all blocks' partials
        int t = threadIdx.x;
        int Btot = gridDim.x;
        sh[t] = (t < Btot) ? g_pG[t] : 0.0f;
        __syncthreads();
        for (int s = 128; s > 0; s >>= 1) {
            if (t < s) sh[t] += sh[t + s];
            __syncthreads();
        }
        if (t == 0) out[0] = sh[0];
    }
}

extern "C" void kernel_launch(void* const* d_in, const int* in_sizes, int n_in,
                              void* d_out, int out_size) {
    const float* hg       = (const float*)d_in[0];
    const float* corr     = (const float*)d_in[1];
    const float* all_emb  = (const float*)d_in[2];
    const int*   sz_idx   = (const int*)d_in[3];
    const int*   nsz_idx  = (const int*)d_in[4];
    const int*   Psz_idx  = (const int*)d_in[5];
    const int*   Pnsz_idx = (const int*)d_in[6];
    float* out = (float*)d_out;

    int nrows = in_sizes[0] / L;          // 32768
    int Ns    = in_sizes[3];
    int Nn    = in_sizes[4];
    int nPsz  = in_sizes[5];
    int nPnsz = in_sizes[6];

    rowpass_kernel<<<RP_BLOCKS, RP_THREADS>>>(hg, nrows, corr, all_emb,
                                              Psz_idx, nPsz, Pnsz_idx, nPnsz);

    int Bsz = (Ns + 255) / 256;
    int Bn  = (Nn + 255) / 256;
    gather_finalize_kernel<<<Bsz + Bn, 256>>>(sz_idx, Ns, nsz_idx, Nn, Bsz,
                                              1.0f / (float)Ns, 1.0f / (float)Nn,
                                              out);
}